// round 14
// baseline (speedup 1.0000x reference)
#include <cuda_runtime.h>
#include <cuda_bf16.h>
#include <cstdint>

#define NN 20000
#define NE 160000
#define HH 8
#define DD 256
#define NSEG (3 * NN)
#define NSLOT (3 * NE)

// ---------------- scratch (static device arrays; no allocation) ----------------
__device__ float g_q[NN * DD];
__device__ float g_k[NN * DD];
__device__ float g_v[NN * DD];
__device__ float g_qf[3][NN * DD];     // F[t] @ q  per causal type t
__device__ float g_A[3][NN * DD];
__device__ float g_C[3][NN * DD];
__device__ int   g_cnt[NSEG];
__device__ int   g_off[NSEG + 1];
__device__ int   g_cur[NSEG];
__device__ int   g_csr[NSLOT];
__device__ __align__(16) __nv_bfloat16 g_x1[NN * DD];
__device__ __align__(16) __nv_bfloat16 g_x2[NN * DD];
__device__ __align__(16) __nv_bfloat16 g_B1[3 * DD * DD];  // [mat][n][k] = W[k][n] hi
__device__ __align__(16) __nv_bfloat16 g_B2[3 * DD * DD];  // lo

typedef unsigned long long ull;

__device__ __forceinline__ void ffma2(ull& a, ull x, ull w) {
    asm("fma.rn.f32x2 %0, %1, %2, %0;" : "+l"(a) : "l"(x), "l"(w));
}
__device__ __forceinline__ ull dup2(float v) {
    ull r; asm("mov.b64 %0, {%1, %1};" : "=l"(r) : "f"(v)); return r;
}
union F4U { float4 f; ull u[2]; };

__device__ __forceinline__ void fma4(float4& a, float s, const float4 b) {
    a.x += s * b.x; a.y += s * b.y; a.z += s * b.z; a.w += s * b.w;
}
__device__ __forceinline__ float4 scale4(float4 a, float s) {
    return make_float4(a.x * s, a.y * s, a.z * s, a.w * s);
}

__device__ __forceinline__ uint32_t smem_u32(const void* p) {
    uint32_t a;
    asm("{ .reg .u64 t; cvta.to.shared.u64 t, %1; cvt.u32.u64 %0, t; }" : "=r"(a) : "l"(p));
    return a;
}
__device__ __forceinline__ void ldsm4(uint32_t* r, uint32_t addr) {
    asm volatile("ldmatrix.sync.aligned.m8n8.x4.shared.b16 {%0,%1,%2,%3}, [%4];"
                 : "=r"(r[0]), "=r"(r[1]), "=r"(r[2]), "=r"(r[3]) : "r"(addr));
}
__device__ __forceinline__ void mma_bf16(float* d, const uint32_t* a, const uint32_t* b) {
    asm volatile(
        "mma.sync.aligned.m16n8k16.row.col.f32.bf16.bf16.f32 "
        "{%0,%1,%2,%3}, {%4,%5,%6,%7}, {%8,%9}, {%0,%1,%2,%3};"
        : "+f"(d[0]), "+f"(d[1]), "+f"(d[2]), "+f"(d[3])
        : "r"(a[0]), "r"(a[1]), "r"(a[2]), "r"(a[3]), "r"(b[0]), "r"(b[1]));
}
__device__ __forceinline__ void cp16(uint32_t saddr, const void* gptr) {
    asm volatile("cp.async.cg.shared.global [%0], [%1], 16;"
                 :: "r"(saddr), "l"(gptr) : "memory");
}

// ---------------- split kernels ----------------
__global__ __launch_bounds__(256) void k_splitx(const float* __restrict__ x) {
    int i = blockIdx.x * 256 + threadIdx.x;
    float v = x[i];
    __nv_bfloat16 h = __float2bfloat16(v);
    g_x1[i] = h;
    g_x2[i] = __float2bfloat16(v - __bfloat162float(h));
}

__global__ __launch_bounds__(256) void k_splitw(
    const float* __restrict__ Wq, const float* __restrict__ Wk, const float* __restrict__ Wv)
{
    int i = blockIdx.x * 256 + threadIdx.x;   // [0, 3*65536)
    int mat = i >> 16;
    int rem = i & 65535;
    int kk = rem >> 8;
    int n  = rem & 255;
    const float* W = (mat == 0) ? Wq : (mat == 1) ? Wk : Wv;
    float v = W[kk * DD + n];
    __nv_bfloat16 h = __float2bfloat16(v);
    g_B1[mat * 65536 + n * DD + kk] = h;
    g_B2[mat * 65536 + n * DD + kk] = __float2bfloat16(v - __bfloat162float(h));
}

__global__ __launch_bounds__(256) void k_zero() {
    int i = blockIdx.x * 256 + threadIdx.x;
    if (i < NSEG) g_cnt[i] = 0;
}

// ---------------- K1: projections via mma.sync bf16 split-GEMM ----------------
#define TSZ   18432           // 128 rows * 144 B (64 bf16 data + 8 pad)
#define BUFSZ (4 * TSZ)
#define GSMEM (2 * BUFSZ)     // 147456

__global__ __launch_bounds__(256, 1) void k_gemm(
    const float* __restrict__ bq, const float* __restrict__ bk, const float* __restrict__ bv)
{
    extern __shared__ char smem[];
    const uint32_t sb = smem_u32(smem);
    const int tid = threadIdx.x, wid = tid >> 5, lane = tid & 31;
    const int m0  = blockIdx.x * 128;
    const int sel = blockIdx.y;
    const int mat = sel >> 1;
    const int n0  = (sel & 1) * 128;
    const size_t bbase = (size_t)mat * 65536;

    const int m_off = (wid >> 2) * 64;
    const int n_off = (wid & 3) * 32;

    const int aj = lane >> 3;
    const int a_row = (lane & 7) + 8 * (aj & 1);
    const int a_kof = 8 * (aj >> 1);
    const int b_nof = (lane & 7) + 8 * (aj >> 1);
    const int b_kof = 8 * (aj & 1);

    auto load_chunk = [&](int c) {
        const int k0 = c * 64;
        const uint32_t bufb = sb + (c & 1) * BUFSZ;
        #pragma unroll
        for (int i = 0; i < 16; i++) {
            int L = i * 256 + tid;
            int tile = L >> 10;
            int r = L & 1023;
            int row = r >> 3;
            int c16 = r & 7;
            uint32_t saddr = bufb + tile * TSZ + row * 144 + c16 * 16;
            const __nv_bfloat16* gp;
            if (tile < 2) {
                int node = min(m0 + row, NN - 1);
                gp = (tile == 0 ? g_x1 : g_x2) + (size_t)node * DD + k0 + c16 * 8;
            } else {
                int nrow = n0 + row;
                gp = (tile == 2 ? g_B1 : g_B2) + bbase + (size_t)nrow * DD + k0 + c16 * 8;
            }
            cp16(saddr, gp);
        }
        asm volatile("cp.async.commit_group;" ::: "memory");
    };

    float dacc[4][4][4];
    #pragma unroll
    for (int mf = 0; mf < 4; mf++)
        #pragma unroll
        for (int nf = 0; nf < 4; nf++)
            #pragma unroll
            for (int rr = 0; rr < 4; rr++) dacc[mf][nf][rr] = 0.0f;

    load_chunk(0);

    #pragma unroll 1
    for (int c = 0; c < 4; c++) {
        if (c + 1 < 4) {
            load_chunk(c + 1);
            asm volatile("cp.async.wait_group 1;" ::: "memory");
        } else {
            asm volatile("cp.async.wait_group 0;" ::: "memory");
        }
        __syncthreads();

        const uint32_t bufb = sb + (c & 1) * BUFSZ;
        const uint32_t A1b = bufb + 0 * TSZ;
        const uint32_t A2b = bufb + 1 * TSZ;
        const uint32_t B1b = bufb + 2 * TSZ;
        const uint32_t B2b = bufb + 3 * TSZ;

        #pragma unroll
        for (int ks = 0; ks < 4; ks++) {
            const int k16 = ks * 16;
            uint32_t af[4][4];
            uint32_t b1f[4][2], b2f[4][2];

            #pragma unroll
            for (int mf = 0; mf < 4; mf++)
                ldsm4(af[mf], A1b + (m_off + mf * 16 + a_row) * 144 + (k16 + a_kof) * 2);
            #pragma unroll
            for (int p = 0; p < 2; p++) {
                uint32_t t4[4];
                ldsm4(t4, B1b + (n_off + p * 16 + b_nof) * 144 + (k16 + b_kof) * 2);
                b1f[p * 2][0] = t4[0]; b1f[p * 2][1] = t4[1];
                b1f[p * 2 + 1][0] = t4[2]; b1f[p * 2 + 1][1] = t4[3];
                ldsm4(t4, B2b + (n_off + p * 16 + b_nof) * 144 + (k16 + b_kof) * 2);
                b2f[p * 2][0] = t4[0]; b2f[p * 2][1] = t4[1];
                b2f[p * 2 + 1][0] = t4[2]; b2f[p * 2 + 1][1] = t4[3];
            }

            #pragma unroll
            for (int mf = 0; mf < 4; mf++)
                #pragma unroll
                for (int nf = 0; nf < 4; nf++)
                    mma_bf16(dacc[mf][nf], af[mf], b1f[nf]);
            #pragma unroll
            for (int mf = 0; mf < 4; mf++)
                #pragma unroll
                for (int nf = 0; nf < 4; nf++)
                    mma_bf16(dacc[mf][nf], af[mf], b2f[nf]);

            #pragma unroll
            for (int mf = 0; mf < 4; mf++)
                ldsm4(af[mf], A2b + (m_off + mf * 16 + a_row) * 144 + (k16 + a_kof) * 2);
            #pragma unroll
            for (int mf = 0; mf < 4; mf++)
                #pragma unroll
                for (int nf = 0; nf < 4; nf++)
                    mma_bf16(dacc[mf][nf], af[mf], b1f[nf]);
        }
        __syncthreads();
    }

    const float* bias = (mat == 0) ? bq : (mat == 1) ? bk : bv;
    float* O          = (mat == 0) ? g_q : (mat == 1) ? g_k : g_v;

    const int trow = lane >> 2;
    const int tcol = (lane & 3) * 2;
    #pragma unroll
    for (int nf = 0; nf < 4; nf++) {
        int gcol = n0 + n_off + nf * 8 + tcol;
        float bx = bias[gcol], by = bias[gcol + 1];
        #pragma unroll
        for (int mf = 0; mf < 4; mf++) {
            int r0 = m0 + m_off + mf * 16 + trow;
            int r1 = r0 + 8;
            if (r0 < NN) {
                float2 v0 = make_float2(dacc[mf][nf][0] + bx, dacc[mf][nf][1] + by);
                *(float2*)&O[(size_t)r0 * DD + gcol] = v0;
            }
            if (r1 < NN) {
                float2 v1 = make_float2(dacc[mf][nf][2] + bx, dacc[mf][nf][3] + by);
                *(float2*)&O[(size_t)r1 * DD + gcol] = v1;
            }
        }
    }
}

// ---------------- CSR build ----------------
__global__ __launch_bounds__(256) void k_hist(const int* __restrict__ dst) {
    int idx = blockIdx.x * 256 + threadIdx.x;
    int e = idx / NE;
    atomicAdd(&g_cnt[e * NN + dst[idx]], 1);
}

#define SCHUNK 59
__global__ __launch_bounds__(1024) void k_scan() {
    __shared__ int ssum[1024];
    int t = threadIdx.x;
    int base = t * SCHUNK;
    int s = 0;
    #pragma unroll 4
    for (int i = 0; i < SCHUNK; i++) {
        int idx = base + i;
        if (idx < NSEG) s += g_cnt[idx];
    }
    ssum[t] = s;
    __syncthreads();
    for (int off = 1; off < 1024; off <<= 1) {
        int v = 0;
        if (t >= off) v = ssum[t - off];
        __syncthreads();
        if (t >= off) ssum[t] += v;
        __syncthreads();
    }
    int run = (t == 0) ? 0 : ssum[t - 1];
    for (int i = 0; i < SCHUNK; i++) {
        int idx = base + i;
        if (idx < NSEG) {
            int c = g_cnt[idx];
            g_off[idx] = run;
            g_cur[idx] = run;
            run += c;
        }
    }
    if (t == 0) g_off[NSEG] = ssum[1023];
}

__global__ __launch_bounds__(256) void k_fill(const int* __restrict__ src,
                                              const int* __restrict__ dst) {
    int idx = blockIdx.x * 256 + threadIdx.x;
    int e = idx / NE;
    int pos = atomicAdd(&g_cur[e * NN + dst[idx]], 1);
    g_csr[pos] = src[idx];
}

// ---------------- K2: qf[t] = F[t] @ q  (transposed-filter smem, conflict-free) ----------------
__global__ __launch_bounds__(256) void k_qf(const float* __restrict__ cau_filter)
{
    const int h     = blockIdx.y;
    const int node0 = blockIdx.x * 32;
    const int tid   = threadIdx.x;

    __shared__ float Fft[3][32 * 36];   // [type][f*36 + d]  (transposed)
    __shared__ float qt[32 * 36];       // [n*36 + f]

    #pragma unroll
    for (int t = 0; t < 3; t++)
        #pragma unroll
        for (int i = 0; i < 4; i++) {
            int idx = i * 256 + tid;          // d*32 + f
            int dd = idx >> 5, f = idx & 31;
            Fft[t][f * 36 + dd] = cau_filter[(size_t)(t * HH + h) * 1024 + idx];
        }
    #pragma unroll
    for (int i = 0; i < 4; i++) {
        int lin = i * 256 + tid;
        int n = lin >> 5, f = lin & 31;
        qt[n * 36 + f] = g_q[(size_t)(node0 + n) * 256 + h * 32 + f];
    }
    __syncthreads();

    const int n = tid >> 3;
    const int g = tid & 7;     // owns d = g*4..g*4+3

    float4 acc0 = make_float4(0,0,0,0);
    float4 acc1 = make_float4(0,0,0,0);
    float4 acc2 = make_float4(0,0,0,0);
    #pragma unroll 8
    for (int f = 0; f < 32; f++) {
        float qv = qt[n * 36 + f];
        fma4(acc0, qv, *(const float4*)&Fft[0][f * 36 + g * 4]);
        fma4(acc1, qv, *(const float4*)&Fft[1][f * 36 + g * 4]);
        fma4(acc2, qv, *(const float4*)&Fft[2][f * 36 + g * 4]);
    }

    size_t o = (size_t)(node0 + n) * 256 + h * 32 + g * 4;
    *(float4*)&g_qf[0][o] = acc0;
    *(float4*)&g_qf[1][o] = acc1;
    *(float4*)&g_qf[2][o] = acc2;
}

// ---------------- K3: warp-per-(e,d) segment — gathers k,v only ----------------
// catt = k[s] . (F[ct(s)] @ q[d]); all 3 qf variants preloaded in registers,
// selected per edge by cau_type[s] (broadcast 4B load, L2-hot 80KB array).
__global__ __launch_bounds__(256) void k_edge2(
    const float* __restrict__ pri, const float* __restrict__ pri_cau,
    const int* __restrict__ cau_type)
{
    int wseg = blockIdx.x * 8 + (threadIdx.x >> 5);
    if (wseg >= NSEG) return;
    int e = wseg / NN;
    int d = wseg - e * NN;
    int lane = threadIdx.x & 31;
    int h = lane >> 2;
    int off = h * 32 + (lane & 3) * 8;

    int beg = g_off[wseg];
    int end = g_off[wseg + 1];

    const float inv = 0.17677669529663688f;
    float pe  = pri[e * 8 + h] * inv;
    float pce = pri_cau[e * 8 + h] * inv;

    const float4* qp = (const float4*)(g_q + (size_t)d * 256 + off);
    float4 q0 = qp[0], q1 = qp[1];
    const float4* f0p = (const float4*)(g_qf[0] + (size_t)d * 256 + off);
    const float4* f1p = (const float4*)(g_qf[1] + (size_t)d * 256 + off);
    const float4* f2p = (const float4*)(g_qf[2] + (size_t)d * 256 + off);
    float4 f00 = f0p[0], f01 = f0p[1];
    float4 f10 = f1p[0], f11 = f1p[1];
    float4 f20 = f2p[0], f21 = f2p[1];

    float4 A0 = make_float4(0,0,0,0), A1 = make_float4(0,0,0,0);
    float4 C0 = make_float4(0,0,0,0), C1 = make_float4(0,0,0,0);
    float sum = 0.0f, csum = 0.0f;

    for (int slot = beg; slot < end; slot++) {
        int s = g_csr[slot];
        int ct = cau_type[s];
        const float4* kp = (const float4*)(g_k + (size_t)s * 256 + off);
        const float4* vp = (const float4*)(g_v + (size_t)s * 256 + off);
        float4 k0 = kp[0], k1 = kp[1];
        float4 v0 = vp[0], v1 = vp[1];

        float4 m0 = (ct == 0) ? f00 : (ct == 1) ? f10 : f20;
        float4 m1 = (ct == 0) ? f01 : (ct == 1) ? f11 : f21;

        float p  = q0.x*k0.x + q0.y*k0.y + q0.z*k0.z + q0.w*k0.w
                 + q1.x*k1.x + q1.y*k1.y + q1.z*k1.z + q1.w*k1.w;
        float pc = m0.x*k0.x + m0.y*k0.y + m0.z*k0.z + m0.w*k0.w
                 + m1.x*k1.x + m1.y*k1.y + m1.z*k1.z + m1.w*k1.w;
        p  += __shfl_xor_sync(0xffffffffu, p, 1);
        p  += __shfl_xor_sync(0xffffffffu, p, 2);
        pc += __shfl_xor_sync(0xffffffffu, pc, 1);
        pc += __shfl_xor_sync(0xffffffffu, pc, 2);

        // logits ~ N(0,1): exp safe; softmax shift-invariant -> no segment max
        float ea  = __expf(p * pe);
        float cea = __expf(pc * pce);

        fma4(A0, ea, v0);  fma4(A1, ea, v1);
        fma4(C0, cea, v0); fma4(C1, cea, v1);
        sum += ea; csum += cea;
    }

    float ia = (end > beg) ? 1.0f / (3.0f * sum)  : 0.0f;
    float ic = (end > beg) ? 1.0f / (3.0f * csum) : 0.0f;

    float4* pa = (float4*)(g_A[e] + (size_t)d * 256 + off);
    float4* pc = (float4*)(g_C[e] + (size_t)d * 256 + off);
    pa[0] = scale4(A0, ia); pa[1] = scale4(A1, ia);
    pc[0] = scale4(C0, ic); pc[1] = scale4(C1, ic);
}

// ---------------- K4: deferred transforms + mean + relu (f32x2) ----------------
__global__ __launch_bounds__(256) void k_post(
    const float* __restrict__ msg, const float* __restrict__ msg_cau,
    const float* __restrict__ comb_pri, const float* __restrict__ time_emb,
    float* __restrict__ out)
{
    const int h     = blockIdx.y;
    const int node0 = blockIdx.x * 32;
    const int tid   = threadIdx.x;

    __shared__ __align__(16) float Mm[3][1024];
    __shared__ __align__(16) float Mc[3][1024];
    __shared__ float at[3][32 * 33];
    __shared__ float ct[3][32 * 33];
    __shared__ float swc_s[3][32];

    #pragma unroll
    for (int e = 0; e < 3; e++)
        #pragma unroll
        for (int i = 0; i < 4; i++) {
            int idx = i * 256 + tid;
            Mm[e][idx] = msg[(size_t)(e * HH + h) * 1024 + idx];
            Mc[e][idx] = msg_cau[(size_t)(e * HH + h) * 1024 + idx]
                       * comb_pri[e * 256 + h * 32 + (idx & 31)];
        }
    if (tid < 96) {
        int e = tid >> 5, n = tid & 31;
        int seg = e * NN + node0 + n;
        swc_s[e][n] = (g_off[seg + 1] > g_off[seg]) ? (1.0f / 3.0f) : 0.0f;
    }
    __syncthreads();

    #pragma unroll
    for (int e = 0; e < 3; e++)
        #pragma unroll
        for (int i = 0; i < 4; i++) {
            int lin = i * 256 + tid;
            int n = lin >> 5, dd = lin & 31;
            int node = node0 + n;
            at[e][n * 33 + dd] = g_A[e][(size_t)node * 256 + h * 32 + dd];
            ct[e][n * 33 + dd] = g_C[e][(size_t)node * 256 + h * 32 + dd]
                               + swc_s[e][n] * time_emb[h * 32 + dd];
        }
    __syncthreads();

    const int n  = tid >> 3;
    const int fq = tid & 7;

    ull a0 = 0ull, a1 = 0ull;
    #pragma unroll
    for (int e = 0; e < 3; e++) {
        const float4* Mmp = (const float4*)Mm[e];
        const float4* Mcp = (const float4*)Mc[e];
        #pragma unroll 8
        for (int d = 0; d < 32; d++) {
            ull ax = dup2(at[e][n * 33 + d]);
            ull cx = dup2(ct[e][n * 33 + d]);
            F4U m; m.f = Mmp[d * 8 + fq];
            F4U c; c.f = Mcp[d * 8 + fq];
            ffma2(a0, ax, m.u[0]); ffma2(a1, ax, m.u[1]);
            ffma2(a0, cx, c.u[0]); ffma2(a1, cx, c.u[1]);
        }
    }

    float2 lo = *(float2*)&a0;
    float2 hi = *(float2*)&a1;
    float4 r;
    r.x = fmaxf(lo.x, 0.0f); r.y = fmaxf(lo.y, 0.0f);
    r.z = fmaxf(hi.x, 0.0f); r.w = fmaxf(hi.y, 0.0f);
    *(float4*)&out[(size_t)(node0 + n) * 256 + h * 32 + fq * 4] = r;
}

extern "C" void kernel_launch(void* const* d_in, const int* in_sizes, int n_in,
                              void* d_out, int out_size)
{
    const float* x    = (const float*)d_in[0];
    const float* Wk_  = (const float*)d_in[1];
    const float* bk_  = (const float*)d_in[2];
    const float* Wq_  = (const float*)d_in[3];
    const float* bq_  = (const float*)d_in[4];
    const float* Wv_  = (const float*)d_in[5];
    const float* bv_  = (const float*)d_in[6];
    const float* pri  = (const float*)d_in[7];
    const float* msg  = (const float*)d_in[8];
    const float* pric = (const float*)d_in[9];
    const float* msgc = (const float*)d_in[10];
    const float* cpri = (const float*)d_in[11];
    const float* cauf = (const float*)d_in[12];
    const float* temb = (const float*)d_in[13];
    const int*   ctyp = (const int*)d_in[14];
    const int*   src  = (const int*)d_in[15];
    const int*   dst  = (const int*)d_in[16];
    float* out = (float*)d_out;

    cudaFuncSetAttribute(k_gemm, cudaFuncAttributeMaxDynamicSharedMemorySize, GSMEM);

    k_splitx<<<NN * DD / 256, 256>>>(x);                                // 1
    k_splitw<<<3 * DD * DD / 256, 256>>>(Wq_, Wk_, Wv_);                // 2
    k_zero  <<<(NSEG + 255) / 256, 256>>>();                            // 3
    k_gemm  <<<dim3((NN + 127) / 128, 6), 256, GSMEM>>>(bq_, bk_, bv_); // 4 <- profiled
    k_hist  <<<NSLOT / 256, 256>>>(dst);                                // 5
    k_scan  <<<1, 1024>>>();                                            // 6
    k_fill  <<<NSLOT / 256, 256>>>(src, dst);                           // 7
    k_qf    <<<dim3(NN / 32, HH), 256>>>(cauf);                         // 8
    k_edge2 <<<(NSEG + 7) / 8, 256>>>(pri, pric, ctyp);                 // 9
    k_post  <<<dim3(NN / 32, HH), 256>>>(msg, msgc, cpri, temb, out);   // 10
}

// round 15
// speedup vs baseline: 1.1796x; 1.1796x over previous
#include <cuda_runtime.h>
#include <cuda_bf16.h>
#include <cuda_fp16.h>
#include <cstdint>

#define NN 20000
#define NE 160000
#define HH 8
#define DD 256
#define NSEG (3 * NN)
#define NSLOT (3 * NE)

// ---------------- scratch (static device arrays; no allocation) ----------------
__device__ float g_q[NN * DD];
__device__ float g_k[NN * DD];
__device__ float g_v[NN * DD];
__device__ float g_mk[NN * DD];
__device__ __align__(16) __half g_Ah[3][NN * DD];   // fp16 normalized A
__device__ __align__(16) __half g_Ch[3][NN * DD];   // fp16 normalized C
__device__ int   g_cnt[NSEG];
__device__ int   g_off[NSEG + 1];
__device__ int   g_cur[NSEG];
__device__ int   g_csr[NSLOT];
__device__ __align__(16) __nv_bfloat16 g_x1[NN * DD];
__device__ __align__(16) __nv_bfloat16 g_x2[NN * DD];
__device__ __align__(16) __nv_bfloat16 g_B1[3 * DD * DD];  // [mat][n][k] = W[k][n] hi
__device__ __align__(16) __nv_bfloat16 g_B2[3 * DD * DD];  // lo

typedef unsigned long long ull;

__device__ __forceinline__ void ffma2(ull& a, ull x, ull w) {
    asm("fma.rn.f32x2 %0, %1, %2, %0;" : "+l"(a) : "l"(x), "l"(w));
}
__device__ __forceinline__ ull dup2(float v) {
    ull r; asm("mov.b64 %0, {%1, %1};" : "=l"(r) : "f"(v)); return r;
}
union F4U { float4 f; ull u[2]; };
union H2U { __half2 h; unsigned u; };

__device__ __forceinline__ void fma4(float4& a, float s, const float4 b) {
    a.x += s * b.x; a.y += s * b.y; a.z += s * b.z; a.w += s * b.w;
}

// pack 8 scaled floats -> 8 fp16 in a uint4
__device__ __forceinline__ uint4 pack_half8(float4 a, float4 b, float s) {
    H2U h0, h1, h2, h3;
    h0.h = __floats2half2_rn(a.x * s, a.y * s);
    h1.h = __floats2half2_rn(a.z * s, a.w * s);
    h2.h = __floats2half2_rn(b.x * s, b.y * s);
    h3.h = __floats2half2_rn(b.z * s, b.w * s);
    uint4 r; r.x = h0.u; r.y = h1.u; r.z = h2.u; r.w = h3.u;
    return r;
}

__device__ __forceinline__ uint32_t smem_u32(const void* p) {
    uint32_t a;
    asm("{ .reg .u64 t; cvta.to.shared.u64 t, %1; cvt.u32.u64 %0, t; }" : "=r"(a) : "l"(p));
    return a;
}
__device__ __forceinline__ void ldsm4(uint32_t* r, uint32_t addr) {
    asm volatile("ldmatrix.sync.aligned.m8n8.x4.shared.b16 {%0,%1,%2,%3}, [%4];"
                 : "=r"(r[0]), "=r"(r[1]), "=r"(r[2]), "=r"(r[3]) : "r"(addr));
}
__device__ __forceinline__ void mma_bf16(float* d, const uint32_t* a, const uint32_t* b) {
    asm volatile(
        "mma.sync.aligned.m16n8k16.row.col.f32.bf16.bf16.f32 "
        "{%0,%1,%2,%3}, {%4,%5,%6,%7}, {%8,%9}, {%0,%1,%2,%3};"
        : "+f"(d[0]), "+f"(d[1]), "+f"(d[2]), "+f"(d[3])
        : "r"(a[0]), "r"(a[1]), "r"(a[2]), "r"(a[3]), "r"(b[0]), "r"(b[1]));
}
__device__ __forceinline__ void cp16(uint32_t saddr, const void* gptr) {
    asm volatile("cp.async.cg.shared.global [%0], [%1], 16;"
                 :: "r"(saddr), "l"(gptr) : "memory");
}

// ---------------- split kernels (k_zero fused into k_splitx) ----------------
__global__ __launch_bounds__(256) void k_splitx(const float* __restrict__ x) {
    int i = blockIdx.x * 256 + threadIdx.x;
    float v = x[i];
    __nv_bfloat16 h = __float2bfloat16(v);
    g_x1[i] = h;
    g_x2[i] = __float2bfloat16(v - __bfloat162float(h));
    if (i < NSEG) g_cnt[i] = 0;
}

__global__ __launch_bounds__(256) void k_splitw(
    const float* __restrict__ Wq, const float* __restrict__ Wk, const float* __restrict__ Wv)
{
    int i = blockIdx.x * 256 + threadIdx.x;   // [0, 3*65536)
    int mat = i >> 16;
    int rem = i & 65535;
    int kk = rem >> 8;
    int n  = rem & 255;
    const float* W = (mat == 0) ? Wq : (mat == 1) ? Wk : Wv;
    float v = W[kk * DD + n];
    __nv_bfloat16 h = __float2bfloat16(v);
    g_B1[mat * 65536 + n * DD + kk] = h;
    g_B2[mat * 65536 + n * DD + kk] = __float2bfloat16(v - __bfloat162float(h));
}

// ---------------- K1: projections via mma.sync bf16 split-GEMM ----------------
#define TSZ   18432           // 128 rows * 144 B (64 bf16 data + 8 pad)
#define BUFSZ (4 * TSZ)
#define GSMEM (2 * BUFSZ)     // 147456

__global__ __launch_bounds__(256, 1) void k_gemm(
    const float* __restrict__ bq, const float* __restrict__ bk, const float* __restrict__ bv)
{
    extern __shared__ char smem[];
    const uint32_t sb = smem_u32(smem);
    const int tid = threadIdx.x, wid = tid >> 5, lane = tid & 31;
    const int m0  = blockIdx.x * 128;
    const int sel = blockIdx.y;
    const int mat = sel >> 1;
    const int n0  = (sel & 1) * 128;
    const size_t bbase = (size_t)mat * 65536;

    const int m_off = (wid >> 2) * 64;
    const int n_off = (wid & 3) * 32;

    const int aj = lane >> 3;
    const int a_row = (lane & 7) + 8 * (aj & 1);
    const int a_kof = 8 * (aj >> 1);
    const int b_nof = (lane & 7) + 8 * (aj >> 1);
    const int b_kof = 8 * (aj & 1);

    auto load_chunk = [&](int c) {
        const int k0 = c * 64;
        const uint32_t bufb = sb + (c & 1) * BUFSZ;
        #pragma unroll
        for (int i = 0; i < 16; i++) {
            int L = i * 256 + tid;
            int tile = L >> 10;
            int r = L & 1023;
            int row = r >> 3;
            int c16 = r & 7;
            uint32_t saddr = bufb + tile * TSZ + row * 144 + c16 * 16;
            const __nv_bfloat16* gp;
            if (tile < 2) {
                int node = min(m0 + row, NN - 1);
                gp = (tile == 0 ? g_x1 : g_x2) + (size_t)node * DD + k0 + c16 * 8;
            } else {
                int nrow = n0 + row;
                gp = (tile == 2 ? g_B1 : g_B2) + bbase + (size_t)nrow * DD + k0 + c16 * 8;
            }
            cp16(saddr, gp);
        }
        asm volatile("cp.async.commit_group;" ::: "memory");
    };

    float dacc[4][4][4];
    #pragma unroll
    for (int mf = 0; mf < 4; mf++)
        #pragma unroll
        for (int nf = 0; nf < 4; nf++)
            #pragma unroll
            for (int rr = 0; rr < 4; rr++) dacc[mf][nf][rr] = 0.0f;

    load_chunk(0);

    #pragma unroll 1
    for (int c = 0; c < 4; c++) {
        if (c + 1 < 4) {
            load_chunk(c + 1);
            asm volatile("cp.async.wait_group 1;" ::: "memory");
        } else {
            asm volatile("cp.async.wait_group 0;" ::: "memory");
        }
        __syncthreads();

        const uint32_t bufb = sb + (c & 1) * BUFSZ;
        const uint32_t A1b = bufb + 0 * TSZ;
        const uint32_t A2b = bufb + 1 * TSZ;
        const uint32_t B1b = bufb + 2 * TSZ;
        const uint32_t B2b = bufb + 3 * TSZ;

        #pragma unroll
        for (int ks = 0; ks < 4; ks++) {
            const int k16 = ks * 16;
            uint32_t af[4][4];
            uint32_t b1f[4][2], b2f[4][2];

            #pragma unroll
            for (int mf = 0; mf < 4; mf++)
                ldsm4(af[mf], A1b + (m_off + mf * 16 + a_row) * 144 + (k16 + a_kof) * 2);
            #pragma unroll
            for (int p = 0; p < 2; p++) {
                uint32_t t4[4];
                ldsm4(t4, B1b + (n_off + p * 16 + b_nof) * 144 + (k16 + b_kof) * 2);
                b1f[p * 2][0] = t4[0]; b1f[p * 2][1] = t4[1];
                b1f[p * 2 + 1][0] = t4[2]; b1f[p * 2 + 1][1] = t4[3];
                ldsm4(t4, B2b + (n_off + p * 16 + b_nof) * 144 + (k16 + b_kof) * 2);
                b2f[p * 2][0] = t4[0]; b2f[p * 2][1] = t4[1];
                b2f[p * 2 + 1][0] = t4[2]; b2f[p * 2 + 1][1] = t4[3];
            }

            #pragma unroll
            for (int mf = 0; mf < 4; mf++)
                #pragma unroll
                for (int nf = 0; nf < 4; nf++)
                    mma_bf16(dacc[mf][nf], af[mf], b1f[nf]);
            #pragma unroll
            for (int mf = 0; mf < 4; mf++)
                #pragma unroll
                for (int nf = 0; nf < 4; nf++)
                    mma_bf16(dacc[mf][nf], af[mf], b2f[nf]);

            #pragma unroll
            for (int mf = 0; mf < 4; mf++)
                ldsm4(af[mf], A2b + (m_off + mf * 16 + a_row) * 144 + (k16 + a_kof) * 2);
            #pragma unroll
            for (int mf = 0; mf < 4; mf++)
                #pragma unroll
                for (int nf = 0; nf < 4; nf++)
                    mma_bf16(dacc[mf][nf], af[mf], b1f[nf]);
        }
        __syncthreads();
    }

    const float* bias = (mat == 0) ? bq : (mat == 1) ? bk : bv;
    float* O          = (mat == 0) ? g_q : (mat == 1) ? g_k : g_v;

    const int trow = lane >> 2;
    const int tcol = (lane & 3) * 2;
    #pragma unroll
    for (int nf = 0; nf < 4; nf++) {
        int gcol = n0 + n_off + nf * 8 + tcol;
        float bx = bias[gcol], by = bias[gcol + 1];
        #pragma unroll
        for (int mf = 0; mf < 4; mf++) {
            int r0 = m0 + m_off + mf * 16 + trow;
            int r1 = r0 + 8;
            if (r0 < NN) {
                float2 v0 = make_float2(dacc[mf][nf][0] + bx, dacc[mf][nf][1] + by);
                *(float2*)&O[(size_t)r0 * DD + gcol] = v0;
            }
            if (r1 < NN) {
                float2 v1 = make_float2(dacc[mf][nf][2] + bx, dacc[mf][nf][3] + by);
                *(float2*)&O[(size_t)r1 * DD + gcol] = v1;
            }
        }
    }
}

// ---------------- CSR build ----------------
__global__ __launch_bounds__(256) void k_hist(const int* __restrict__ dst) {
    int idx = blockIdx.x * 256 + threadIdx.x;
    int e = idx / NE;
    atomicAdd(&g_cnt[e * NN + dst[idx]], 1);
}

#define SCHUNK 59
__global__ __launch_bounds__(1024) void k_scan() {
    __shared__ int ssum[1024];
    int t = threadIdx.x;
    int base = t * SCHUNK;
    int s = 0;
    #pragma unroll 4
    for (int i = 0; i < SCHUNK; i++) {
        int idx = base + i;
        if (idx < NSEG) s += g_cnt[idx];
    }
    ssum[t] = s;
    __syncthreads();
    for (int off = 1; off < 1024; off <<= 1) {
        int v = 0;
        if (t >= off) v = ssum[t - off];
        __syncthreads();
        if (t >= off) ssum[t] += v;
        __syncthreads();
    }
    int run = (t == 0) ? 0 : ssum[t - 1];
    for (int i = 0; i < SCHUNK; i++) {
        int idx = base + i;
        if (idx < NSEG) {
            int c = g_cnt[idx];
            g_off[idx] = run;
            g_cur[idx] = run;
            run += c;
        }
    }
    if (t == 0) g_off[NSEG] = ssum[1023];
}

__global__ __launch_bounds__(256) void k_fill(const int* __restrict__ src,
                                              const int* __restrict__ dst) {
    int idx = blockIdx.x * 256 + threadIdx.x;
    int e = idx / NE;
    int pos = atomicAdd(&g_cur[e * NN + dst[idx]], 1);
    g_csr[pos] = src[idx];
}

// ---------------- K2: masked_k ----------------
__global__ __launch_bounds__(256) void k_mk(
    const float* __restrict__ cau_filter, const int* __restrict__ cau_type)
{
    const int h     = blockIdx.y;
    const int node0 = blockIdx.x * 32;
    const int tid   = threadIdx.x;

    __shared__ __align__(16) float Ff[3][1024];
    __shared__ float kt[32 * 33];

    #pragma unroll
    for (int e = 0; e < 3; e++)
        #pragma unroll
        for (int i = 0; i < 4; i++) {
            int idx = i * 256 + tid;
            Ff[e][idx] = cau_filter[(size_t)(e * HH + h) * 1024 + idx];
        }
    #pragma unroll
    for (int i = 0; i < 4; i++) {
        int lin = i * 256 + tid;
        int n = lin >> 5, d = lin & 31;
        kt[n * 33 + d] = g_k[(size_t)(node0 + n) * 256 + h * 32 + d];
    }
    __syncthreads();

    const int n  = tid >> 3;
    const int fq = tid & 7;
    const int ct = cau_type[node0 + n];
    const float4* Ffp = (const float4*)Ff[ct];

    float4 mk = make_float4(0,0,0,0);
    #pragma unroll 8
    for (int d = 0; d < 32; d++)
        fma4(mk, kt[n * 33 + d], Ffp[d * 8 + fq]);

    *(float4*)&g_mk[(size_t)(node0 + n) * 256 + h * 32 + fq * 4] = mk;
}

// ---------------- K3: warp-per-(e,d) segment (round-9 loop, fp16 A/C stores) ----------------
__global__ __launch_bounds__(256) void k_edge2(
    const float* __restrict__ pri, const float* __restrict__ pri_cau)
{
    int wseg = blockIdx.x * 8 + (threadIdx.x >> 5);
    if (wseg >= NSEG) return;
    int e = wseg / NN;
    int d = wseg - e * NN;
    int lane = threadIdx.x & 31;
    int h = lane >> 2;
    int off = h * 32 + (lane & 3) * 8;

    int beg = g_off[wseg];
    int end = g_off[wseg + 1];

    const float inv = 0.17677669529663688f;
    float pe  = pri[e * 8 + h] * inv;
    float pce = pri_cau[e * 8 + h] * inv;

    const float4* qp = (const float4*)(g_q + (size_t)d * 256 + off);
    float4 q0 = qp[0], q1 = qp[1];

    float4 A0 = make_float4(0,0,0,0), A1 = make_float4(0,0,0,0);
    float4 C0 = make_float4(0,0,0,0), C1 = make_float4(0,0,0,0);
    float sum = 0.0f, csum = 0.0f;

    for (int slot = beg; slot < end; slot++) {
        int s = g_csr[slot];
        const float4* kp = (const float4*)(g_k  + (size_t)s * 256 + off);
        const float4* mp = (const float4*)(g_mk + (size_t)s * 256 + off);
        const float4* vp = (const float4*)(g_v  + (size_t)s * 256 + off);
        float4 k0 = kp[0], k1 = kp[1];
        float4 m0 = mp[0], m1 = mp[1];
        float4 v0 = vp[0], v1 = vp[1];

        float p  = q0.x*k0.x + q0.y*k0.y + q0.z*k0.z + q0.w*k0.w
                 + q1.x*k1.x + q1.y*k1.y + q1.z*k1.z + q1.w*k1.w;
        float pc = q0.x*m0.x + q0.y*m0.y + q0.z*m0.z + q0.w*m0.w
                 + q1.x*m1.x + q1.y*m1.y + q1.z*m1.z + q1.w*m1.w;
        p  += __shfl_xor_sync(0xffffffffu, p, 1);
        p  += __shfl_xor_sync(0xffffffffu, p, 2);
        pc += __shfl_xor_sync(0xffffffffu, pc, 1);
        pc += __shfl_xor_sync(0xffffffffu, pc, 2);

        // logits ~ N(0,1): exp safe; softmax shift-invariant -> no segment max
        float ea  = __expf(p * pe);
        float cea = __expf(pc * pce);

        fma4(A0, ea, v0);  fma4(A1, ea, v1);
        fma4(C0, cea, v0); fma4(C1, cea, v1);
        sum += ea; csum += cea;
    }

    float ia = (end > beg) ? 1.0f / (3.0f * sum)  : 0.0f;
    float ic = (end > beg) ? 1.0f / (3.0f * csum) : 0.0f;

    *(uint4*)&g_Ah[e][(size_t)d * 256 + off] = pack_half8(A0, A1, ia);
    *(uint4*)&g_Ch[e][(size_t)d * 256 + off] = pack_half8(C0, C1, ic);
}

// ---------------- K4: deferred transforms + mean + relu (f32x2) ----------------
__global__ __launch_bounds__(256) void k_post(
    const float* __restrict__ msg, const float* __restrict__ msg_cau,
    const float* __restrict__ comb_pri, const float* __restrict__ time_emb,
    float* __restrict__ out)
{
    const int h     = blockIdx.y;
    const int node0 = blockIdx.x * 32;
    const int tid   = threadIdx.x;

    __shared__ __align__(16) float Mm[3][1024];
    __shared__ __align__(16) float Mc[3][1024];
    __shared__ float at[3][32 * 33];
    __shared__ float ct[3][32 * 33];
    __shared__ float swc_s[3][32];

    #pragma unroll
    for (int e = 0; e < 3; e++)
        #pragma unroll
        for (int i = 0; i < 4; i++) {
            int idx = i * 256 + tid;
            Mm[e][idx] = msg[(size_t)(e * HH + h) * 1024 + idx];
            Mc[e][idx] = msg_cau[(size_t)(e * HH + h) * 1024 + idx]
                       * comb_pri[e * 256 + h * 32 + (idx & 31)];
        }
    if (tid < 96) {
        int e = tid >> 5, n = tid & 31;
        int seg = e * NN + node0 + n;
        swc_s[e][n] = (g_off[seg + 1] > g_off[seg]) ? (1.0f / 3.0f) : 0.0f;
    }
    __syncthreads();

    #pragma unroll
    for (int e = 0; e < 3; e++)
        #pragma unroll
        for (int i = 0; i < 4; i++) {
            int lin = i * 256 + tid;
            int n = lin >> 5, dd = lin & 31;
            int node = node0 + n;
            at[e][n * 33 + dd] = __half2float(g_Ah[e][(size_t)node * 256 + h * 32 + dd]);
            ct[e][n * 33 + dd] = __half2float(g_Ch[e][(size_t)node * 256 + h * 32 + dd])
                               + swc_s[e][n] * time_emb[h * 32 + dd];
        }
    __syncthreads();

    const int n  = tid >> 3;
    const int fq = tid & 7;

    ull a0 = 0ull, a1 = 0ull;
    #pragma unroll
    for (int e = 0; e < 3; e++) {
        const float4* Mmp = (const float4*)Mm[e];
        const float4* Mcp = (const float4*)Mc[e];
        #pragma unroll 8
        for (int d = 0; d < 32; d++) {
            ull ax = dup2(at[e][n * 33 + d]);
            ull cx = dup2(ct[e][n * 33 + d]);
            F4U m; m.f = Mmp[d * 8 + fq];
            F4U c; c.f = Mcp[d * 8 + fq];
            ffma2(a0, ax, m.u[0]); ffma2(a1, ax, m.u[1]);
            ffma2(a0, cx, c.u[0]); ffma2(a1, cx, c.u[1]);
        }
    }

    float2 lo = *(float2*)&a0;
    float2 hi = *(float2*)&a1;
    float4 r;
    r.x = fmaxf(lo.x, 0.0f); r.y = fmaxf(lo.y, 0.0f);
    r.z = fmaxf(hi.x, 0.0f); r.w = fmaxf(hi.y, 0.0f);
    *(float4*)&out[(size_t)(node0 + n) * 256 + h * 32 + fq * 4] = r;
}

extern "C" void kernel_launch(void* const* d_in, const int* in_sizes, int n_in,
                              void* d_out, int out_size)
{
    const float* x    = (const float*)d_in[0];
    const float* Wk_  = (const float*)d_in[1];
    const float* bk_  = (const float*)d_in[2];
    const float* Wq_  = (const float*)d_in[3];
    const float* bq_  = (const float*)d_in[4];
    const float* Wv_  = (const float*)d_in[5];
    const float* bv_  = (const float*)d_in[6];
    const float* pri  = (const float*)d_in[7];
    const float* msg  = (const float*)d_in[8];
    const float* pric = (const float*)d_in[9];
    const float* msgc = (const float*)d_in[10];
    const float* cpri = (const float*)d_in[11];
    const float* cauf = (const float*)d_in[12];
    const float* temb = (const float*)d_in[13];
    const int*   ctyp = (const int*)d_in[14];
    const int*   src  = (const int*)d_in[15];
    const int*   dst  = (const int*)d_in[16];
    float* out = (float*)d_out;

    cudaFuncSetAttribute(k_gemm, cudaFuncAttributeMaxDynamicSharedMemorySize, GSMEM);

    k_splitx<<<NN * DD / 256, 256>>>(x);                                // 1 (cnt zero fused)
    k_splitw<<<3 * DD * DD / 256, 256>>>(Wq_, Wk_, Wv_);                // 2
    k_hist  <<<NSLOT / 256, 256>>>(dst);                                // 3
    k_gemm  <<<dim3((NN + 127) / 128, 6), 256, GSMEM>>>(bq_, bk_, bv_); // 4 <- profiled
    k_scan  <<<1, 1024>>>();                                            // 5
    k_fill  <<<NSLOT / 256, 256>>>(src, dst);                           // 6
    k_mk    <<<dim3(NN / 32, HH), 256>>>(cauf, ctyp);                   // 7
    k_edge2 <<<(NSEG + 7) / 8, 256>>>(pri, pric);                       // 8
    k_post  <<<dim3(NN / 32, HH), 256>>>(msg, msgc, cpri, temb, out);   // 9
}

// round 16
// speedup vs baseline: 1.2301x; 1.0429x over previous
#include <cuda_runtime.h>
#include <cuda_bf16.h>
#include <cuda_fp16.h>
#include <cstdint>

#define NN 20000
#define NE 160000
#define HH 8
#define DD 256
#define NSEG (3 * NN)
#define NSLOT (3 * NE)

// ---------------- scratch (static device arrays; no allocation) ----------------
__device__ float g_q[NN * DD];                       // fp32 (read once per segment)
__device__ __align__(16) __half g_kh[NN * DD];       // fp16 k
__device__ __align__(16) __half g_vh[NN * DD];       // fp16 v
__device__ __align__(16) __half g_mkh[NN * DD];      // fp16 masked_k
__device__ __align__(16) __half g_Ah[3][NN * DD];    // fp16 normalized A
__device__ __align__(16) __half g_Ch[3][NN * DD];    // fp16 normalized C
__device__ int   g_cnt[NSEG];
__device__ int   g_off[NSEG + 1];
__device__ int   g_cur[NSEG];
__device__ int   g_csr[NSLOT];
__device__ __align__(16) __nv_bfloat16 g_x1[NN * DD];
__device__ __align__(16) __nv_bfloat16 g_x2[NN * DD];
__device__ __align__(16) __nv_bfloat16 g_B1[3 * DD * DD];  // [mat][n][k] = W[k][n] hi
__device__ __align__(16) __nv_bfloat16 g_B2[3 * DD * DD];  // lo

typedef unsigned long long ull;

__device__ __forceinline__ void ffma2(ull& a, ull x, ull w) {
    asm("fma.rn.f32x2 %0, %1, %2, %0;" : "+l"(a) : "l"(x), "l"(w));
}
__device__ __forceinline__ ull dup2(float v) {
    ull r; asm("mov.b64 %0, {%1, %1};" : "=l"(r) : "f"(v)); return r;
}
union F4U { float4 f; ull u[2]; };
union H2U { __half2 h; unsigned u; };

__device__ __forceinline__ void fma4(float4& a, float s, const float4 b) {
    a.x += s * b.x; a.y += s * b.y; a.z += s * b.z; a.w += s * b.w;
}

// pack 8 scaled floats -> 8 fp16 in a uint4
__device__ __forceinline__ uint4 pack_half8(float4 a, float4 b, float s) {
    H2U h0, h1, h2, h3;
    h0.h = __floats2half2_rn(a.x * s, a.y * s);
    h1.h = __floats2half2_rn(a.z * s, a.w * s);
    h2.h = __floats2half2_rn(b.x * s, b.y * s);
    h3.h = __floats2half2_rn(b.z * s, b.w * s);
    uint4 r; r.x = h0.u; r.y = h1.u; r.z = h2.u; r.w = h3.u;
    return r;
}
// unpack 8 fp16 (uint4) -> two float4
__device__ __forceinline__ void unpack8(uint4 u, float4& lo, float4& hi) {
    float2 a = __half22float2(*(__half2*)&u.x);
    float2 b = __half22float2(*(__half2*)&u.y);
    float2 c = __half22float2(*(__half2*)&u.z);
    float2 d = __half22float2(*(__half2*)&u.w);
    lo = make_float4(a.x, a.y, b.x, b.y);
    hi = make_float4(c.x, c.y, d.x, d.y);
}

__device__ __forceinline__ uint32_t smem_u32(const void* p) {
    uint32_t a;
    asm("{ .reg .u64 t; cvta.to.shared.u64 t, %1; cvt.u32.u64 %0, t; }" : "=r"(a) : "l"(p));
    return a;
}
__device__ __forceinline__ void ldsm4(uint32_t* r, uint32_t addr) {
    asm volatile("ldmatrix.sync.aligned.m8n8.x4.shared.b16 {%0,%1,%2,%3}, [%4];"
                 : "=r"(r[0]), "=r"(r[1]), "=r"(r[2]), "=r"(r[3]) : "r"(addr));
}
__device__ __forceinline__ void mma_bf16(float* d, const uint32_t* a, const uint32_t* b) {
    asm volatile(
        "mma.sync.aligned.m16n8k16.row.col.f32.bf16.bf16.f32 "
        "{%0,%1,%2,%3}, {%4,%5,%6,%7}, {%8,%9}, {%0,%1,%2,%3};"
        : "+f"(d[0]), "+f"(d[1]), "+f"(d[2]), "+f"(d[3])
        : "r"(a[0]), "r"(a[1]), "r"(a[2]), "r"(a[3]), "r"(b[0]), "r"(b[1]));
}
__device__ __forceinline__ void cp16(uint32_t saddr, const void* gptr) {
    asm volatile("cp.async.cg.shared.global [%0], [%1], 16;"
                 :: "r"(saddr), "l"(gptr) : "memory");
}

// ---------------- split kernels (k_zero fused into k_splitx) ----------------
__global__ __launch_bounds__(256) void k_splitx(const float* __restrict__ x) {
    int i = blockIdx.x * 256 + threadIdx.x;
    float v = x[i];
    __nv_bfloat16 h = __float2bfloat16(v);
    g_x1[i] = h;
    g_x2[i] = __float2bfloat16(v - __bfloat162float(h));
    if (i < NSEG) g_cnt[i] = 0;
}

__global__ __launch_bounds__(256) void k_splitw(
    const float* __restrict__ Wq, const float* __restrict__ Wk, const float* __restrict__ Wv)
{
    int i = blockIdx.x * 256 + threadIdx.x;   // [0, 3*65536)
    int mat = i >> 16;
    int rem = i & 65535;
    int kk = rem >> 8;
    int n  = rem & 255;
    const float* W = (mat == 0) ? Wq : (mat == 1) ? Wk : Wv;
    float v = W[kk * DD + n];
    __nv_bfloat16 h = __float2bfloat16(v);
    g_B1[mat * 65536 + n * DD + kk] = h;
    g_B2[mat * 65536 + n * DD + kk] = __float2bfloat16(v - __bfloat162float(h));
}

// ---------------- K1: projections via mma.sync bf16 split-GEMM ----------------
#define TSZ   18432           // 128 rows * 144 B (64 bf16 data + 8 pad)
#define BUFSZ (4 * TSZ)
#define GSMEM (2 * BUFSZ)     // 147456

__global__ __launch_bounds__(256, 1) void k_gemm(
    const float* __restrict__ bq, const float* __restrict__ bk, const float* __restrict__ bv)
{
    extern __shared__ char smem[];
    const uint32_t sb = smem_u32(smem);
    const int tid = threadIdx.x, wid = tid >> 5, lane = tid & 31;
    const int m0  = blockIdx.x * 128;
    const int sel = blockIdx.y;
    const int mat = sel >> 1;
    const int n0  = (sel & 1) * 128;
    const size_t bbase = (size_t)mat * 65536;

    const int m_off = (wid >> 2) * 64;
    const int n_off = (wid & 3) * 32;

    const int aj = lane >> 3;
    const int a_row = (lane & 7) + 8 * (aj & 1);
    const int a_kof = 8 * (aj >> 1);
    const int b_nof = (lane & 7) + 8 * (aj >> 1);
    const int b_kof = 8 * (aj & 1);

    auto load_chunk = [&](int c) {
        const int k0 = c * 64;
        const uint32_t bufb = sb + (c & 1) * BUFSZ;
        #pragma unroll
        for (int i = 0; i < 16; i++) {
            int L = i * 256 + tid;
            int tile = L >> 10;
            int r = L & 1023;
            int row = r >> 3;
            int c16 = r & 7;
            uint32_t saddr = bufb + tile * TSZ + row * 144 + c16 * 16;
            const __nv_bfloat16* gp;
            if (tile < 2) {
                int node = min(m0 + row, NN - 1);
                gp = (tile == 0 ? g_x1 : g_x2) + (size_t)node * DD + k0 + c16 * 8;
            } else {
                int nrow = n0 + row;
                gp = (tile == 2 ? g_B1 : g_B2) + bbase + (size_t)nrow * DD + k0 + c16 * 8;
            }
            cp16(saddr, gp);
        }
        asm volatile("cp.async.commit_group;" ::: "memory");
    };

    float dacc[4][4][4];
    #pragma unroll
    for (int mf = 0; mf < 4; mf++)
        #pragma unroll
        for (int nf = 0; nf < 4; nf++)
            #pragma unroll
            for (int rr = 0; rr < 4; rr++) dacc[mf][nf][rr] = 0.0f;

    load_chunk(0);

    #pragma unroll 1
    for (int c = 0; c < 4; c++) {
        if (c + 1 < 4) {
            load_chunk(c + 1);
            asm volatile("cp.async.wait_group 1;" ::: "memory");
        } else {
            asm volatile("cp.async.wait_group 0;" ::: "memory");
        }
        __syncthreads();

        const uint32_t bufb = sb + (c & 1) * BUFSZ;
        const uint32_t A1b = bufb + 0 * TSZ;
        const uint32_t A2b = bufb + 1 * TSZ;
        const uint32_t B1b = bufb + 2 * TSZ;
        const uint32_t B2b = bufb + 3 * TSZ;

        #pragma unroll
        for (int ks = 0; ks < 4; ks++) {
            const int k16 = ks * 16;
            uint32_t af[4][4];
            uint32_t b1f[4][2], b2f[4][2];

            #pragma unroll
            for (int mf = 0; mf < 4; mf++)
                ldsm4(af[mf], A1b + (m_off + mf * 16 + a_row) * 144 + (k16 + a_kof) * 2);
            #pragma unroll
            for (int p = 0; p < 2; p++) {
                uint32_t t4[4];
                ldsm4(t4, B1b + (n_off + p * 16 + b_nof) * 144 + (k16 + b_kof) * 2);
                b1f[p * 2][0] = t4[0]; b1f[p * 2][1] = t4[1];
                b1f[p * 2 + 1][0] = t4[2]; b1f[p * 2 + 1][1] = t4[3];
                ldsm4(t4, B2b + (n_off + p * 16 + b_nof) * 144 + (k16 + b_kof) * 2);
                b2f[p * 2][0] = t4[0]; b2f[p * 2][1] = t4[1];
                b2f[p * 2 + 1][0] = t4[2]; b2f[p * 2 + 1][1] = t4[3];
            }

            #pragma unroll
            for (int mf = 0; mf < 4; mf++)
                #pragma unroll
                for (int nf = 0; nf < 4; nf++)
                    mma_bf16(dacc[mf][nf], af[mf], b1f[nf]);
            #pragma unroll
            for (int mf = 0; mf < 4; mf++)
                #pragma unroll
                for (int nf = 0; nf < 4; nf++)
                    mma_bf16(dacc[mf][nf], af[mf], b2f[nf]);

            #pragma unroll
            for (int mf = 0; mf < 4; mf++)
                ldsm4(af[mf], A2b + (m_off + mf * 16 + a_row) * 144 + (k16 + a_kof) * 2);
            #pragma unroll
            for (int mf = 0; mf < 4; mf++)
                #pragma unroll
                for (int nf = 0; nf < 4; nf++)
                    mma_bf16(dacc[mf][nf], af[mf], b1f[nf]);
        }
        __syncthreads();
    }

    const float* bias = (mat == 0) ? bq : (mat == 1) ? bk : bv;
    __half* Oh = (mat == 1) ? g_kh : g_vh;

    const int trow = lane >> 2;
    const int tcol = (lane & 3) * 2;
    #pragma unroll
    for (int nf = 0; nf < 4; nf++) {
        int gcol = n0 + n_off + nf * 8 + tcol;
        float bx = bias[gcol], by = bias[gcol + 1];
        #pragma unroll
        for (int mf = 0; mf < 4; mf++) {
            int r0 = m0 + m_off + mf * 16 + trow;
            int r1 = r0 + 8;
            if (mat == 0) {
                if (r0 < NN) {
                    float2 v0 = make_float2(dacc[mf][nf][0] + bx, dacc[mf][nf][1] + by);
                    *(float2*)&g_q[(size_t)r0 * DD + gcol] = v0;
                }
                if (r1 < NN) {
                    float2 v1 = make_float2(dacc[mf][nf][2] + bx, dacc[mf][nf][3] + by);
                    *(float2*)&g_q[(size_t)r1 * DD + gcol] = v1;
                }
            } else {
                if (r0 < NN) {
                    H2U h; h.h = __floats2half2_rn(dacc[mf][nf][0] + bx, dacc[mf][nf][1] + by);
                    *(unsigned*)&Oh[(size_t)r0 * DD + gcol] = h.u;
                }
                if (r1 < NN) {
                    H2U h; h.h = __floats2half2_rn(dacc[mf][nf][2] + bx, dacc[mf][nf][3] + by);
                    *(unsigned*)&Oh[(size_t)r1 * DD + gcol] = h.u;
                }
            }
        }
    }
}

// ---------------- CSR build ----------------
__global__ __launch_bounds__(256) void k_hist(const int* __restrict__ dst) {
    int idx = blockIdx.x * 256 + threadIdx.x;
    int e = idx / NE;
    atomicAdd(&g_cnt[e * NN + dst[idx]], 1);
}

#define SCHUNK 59
__global__ __launch_bounds__(1024) void k_scan() {
    __shared__ int ssum[1024];
    int t = threadIdx.x;
    int base = t * SCHUNK;
    int s = 0;
    #pragma unroll 4
    for (int i = 0; i < SCHUNK; i++) {
        int idx = base + i;
        if (idx < NSEG) s += g_cnt[idx];
    }
    ssum[t] = s;
    __syncthreads();
    for (int off = 1; off < 1024; off <<= 1) {
        int v = 0;
        if (t >= off) v = ssum[t - off];
        __syncthreads();
        if (t >= off) ssum[t] += v;
        __syncthreads();
    }
    int run = (t == 0) ? 0 : ssum[t - 1];
    for (int i = 0; i < SCHUNK; i++) {
        int idx = base + i;
        if (idx < NSEG) {
            int c = g_cnt[idx];
            g_off[idx] = run;
            g_cur[idx] = run;
            run += c;
        }
    }
    if (t == 0) g_off[NSEG] = ssum[1023];
}

__global__ __launch_bounds__(256) void k_fill(const int* __restrict__ src,
                                              const int* __restrict__ dst) {
    int idx = blockIdx.x * 256 + threadIdx.x;
    int e = idx / NE;
    int pos = atomicAdd(&g_cur[e * NN + dst[idx]], 1);
    g_csr[pos] = src[idx];
}

// ---------------- K2: masked_k (fp16 in, fp32 math, fp16 out) ----------------
__global__ __launch_bounds__(256) void k_mk(
    const float* __restrict__ cau_filter, const int* __restrict__ cau_type)
{
    const int h     = blockIdx.y;
    const int node0 = blockIdx.x * 32;
    const int tid   = threadIdx.x;

    __shared__ __align__(16) float Ff[3][1024];
    __shared__ float kt[32 * 33];

    #pragma unroll
    for (int e = 0; e < 3; e++)
        #pragma unroll
        for (int i = 0; i < 4; i++) {
            int idx = i * 256 + tid;
            Ff[e][idx] = cau_filter[(size_t)(e * HH + h) * 1024 + idx];
        }
    #pragma unroll
    for (int i = 0; i < 4; i++) {
        int lin = i * 256 + tid;
        int n = lin >> 5, d = lin & 31;
        kt[n * 33 + d] = __half2float(g_kh[(size_t)(node0 + n) * 256 + h * 32 + d]);
    }
    __syncthreads();

    const int n  = tid >> 3;
    const int fq = tid & 7;
    const int ct = cau_type[node0 + n];
    const float4* Ffp = (const float4*)Ff[ct];

    float4 mk = make_float4(0,0,0,0);
    #pragma unroll 8
    for (int d = 0; d < 32; d++)
        fma4(mk, kt[n * 33 + d], Ffp[d * 8 + fq]);

    H2U h0, h1;
    h0.h = __floats2half2_rn(mk.x, mk.y);
    h1.h = __floats2half2_rn(mk.z, mk.w);
    uint2 packed; packed.x = h0.u; packed.y = h1.u;
    *(uint2*)&g_mkh[(size_t)(node0 + n) * 256 + h * 32 + fq * 4] = packed;
}

// ---------------- K3: warp-per-(e,d) segment — fp16 gathers (half traffic) ----------------
__global__ __launch_bounds__(256) void k_edge2(
    const float* __restrict__ pri, const float* __restrict__ pri_cau)
{
    int wseg = blockIdx.x * 8 + (threadIdx.x >> 5);
    if (wseg >= NSEG) return;
    int e = wseg / NN;
    int d = wseg - e * NN;
    int lane = threadIdx.x & 31;
    int h = lane >> 2;
    int off = h * 32 + (lane & 3) * 8;

    int beg = g_off[wseg];
    int end = g_off[wseg + 1];

    const float inv = 0.17677669529663688f;
    float pe  = pri[e * 8 + h] * inv;
    float pce = pri_cau[e * 8 + h] * inv;

    const float4* qp = (const float4*)(g_q + (size_t)d * 256 + off);
    float4 q0 = qp[0], q1 = qp[1];

    float4 A0 = make_float4(0,0,0,0), A1 = make_float4(0,0,0,0);
    float4 C0 = make_float4(0,0,0,0), C1 = make_float4(0,0,0,0);
    float sum = 0.0f, csum = 0.0f;

    for (int slot = beg; slot < end; slot++) {
        int s = g_csr[slot];
        uint4 ku = *(const uint4*)(g_kh  + (size_t)s * 256 + off);
        uint4 mu = *(const uint4*)(g_mkh + (size_t)s * 256 + off);
        uint4 vu = *(const uint4*)(g_vh  + (size_t)s * 256 + off);
        float4 k0, k1, m0, m1, v0, v1;
        unpack8(ku, k0, k1);
        unpack8(mu, m0, m1);
        unpack8(vu, v0, v1);

        float p  = q0.x*k0.x + q0.y*k0.y + q0.z*k0.z + q0.w*k0.w
                 + q1.x*k1.x + q1.y*k1.y + q1.z*k1.z + q1.w*k1.w;
        float pc = q0.x*m0.x + q0.y*m0.y + q0.z*m0.z + q0.w*m0.w
                 + q1.x*m1.x + q1.y*m1.y + q1.z*m1.z + q1.w*m1.w;
        p  += __shfl_xor_sync(0xffffffffu, p, 1);
        p  += __shfl_xor_sync(0xffffffffu, p, 2);
        pc += __shfl_xor_sync(0xffffffffu, pc, 1);
        pc += __shfl_xor_sync(0xffffffffu, pc, 2);

        // logits ~ N(0,1): exp safe; softmax shift-invariant -> no segment max
        float ea  = __expf(p * pe);
        float cea = __expf(pc * pce);

        fma4(A0, ea, v0);  fma4(A1, ea, v1);
        fma4(C0, cea, v0); fma4(C1, cea, v1);
        sum += ea; csum += cea;
    }

    float ia = (end > beg) ? 1.0f / (3.0f * sum)  : 0.0f;
    float ic = (end > beg) ? 1.0f / (3.0f * csum) : 0.0f;

    *(uint4*)&g_Ah[e][(size_t)d * 256 + off] = pack_half8(A0, A1, ia);
    *(uint4*)&g_Ch[e][(size_t)d * 256 + off] = pack_half8(C0, C1, ic);
}

// ---------------- K4: deferred transforms + mean + relu (f32x2) ----------------
__global__ __launch_bounds__(256) void k_post(
    const float* __restrict__ msg, const float* __restrict__ msg_cau,
    const float* __restrict__ comb_pri, const float* __restrict__ time_emb,
    float* __restrict__ out)
{
    const int h     = blockIdx.y;
    const int node0 = blockIdx.x * 32;
    const int tid   = threadIdx.x;

    __shared__ __align__(16) float Mm[3][1024];
    __shared__ __align__(16) float Mc[3][1024];
    __shared__ float at[3][32 * 33];
    __shared__ float ct[3][32 * 33];
    __shared__ float swc_s[3][32];

    #pragma unroll
    for (int e = 0; e < 3; e++)
        #pragma unroll
        for (int i = 0; i < 4; i++) {
            int idx = i * 256 + tid;
            Mm[e][idx] = msg[(size_t)(e * HH + h) * 1024 + idx];
            Mc[e][idx] = msg_cau[(size_t)(e * HH + h) * 1024 + idx]
                       * comb_pri[e * 256 + h * 32 + (idx & 31)];
        }
    if (tid < 96) {
        int e = tid >> 5, n = tid & 31;
        int seg = e * NN + node0 + n;
        swc_s[e][n] = (g_off[seg + 1] > g_off[seg]) ? (1.0f / 3.0f) : 0.0f;
    }
    __syncthreads();

    #pragma unroll
    for (int e = 0; e < 3; e++)
        #pragma unroll
        for (int i = 0; i < 4; i++) {
            int lin = i * 256 + tid;
            int n = lin >> 5, dd = lin & 31;
            int node = node0 + n;
            at[e][n * 33 + dd] = __half2float(g_Ah[e][(size_t)node * 256 + h * 32 + dd]);
            ct[e][n * 33 + dd] = __half2float(g_Ch[e][(size_t)node * 256 + h * 32 + dd])
                               + swc_s[e][n] * time_emb[h * 32 + dd];
        }
    __syncthreads();

    const int n  = tid >> 3;
    const int fq = tid & 7;

    ull a0 = 0ull, a1 = 0ull;
    #pragma unroll
    for (int e = 0; e < 3; e++) {
        const float4* Mmp = (const float4*)Mm[e];
        const float4* Mcp = (const float4*)Mc[e];
        #pragma unroll 8
        for (int d = 0; d < 32; d++) {
            ull ax = dup2(at[e][n * 33 + d]);
            ull cx = dup2(ct[e][n * 33 + d]);
            F4U m; m.f = Mmp[d * 8 + fq];
            F4U c; c.f = Mcp[d * 8 + fq];
            ffma2(a0, ax, m.u[0]); ffma2(a1, ax, m.u[1]);
            ffma2(a0, cx, c.u[0]); ffma2(a1, cx, c.u[1]);
        }
    }

    float2 lo = *(float2*)&a0;
    float2 hi = *(float2*)&a1;
    float4 r;
    r.x = fmaxf(lo.x, 0.0f); r.y = fmaxf(lo.y, 0.0f);
    r.z = fmaxf(hi.x, 0.0f); r.w = fmaxf(hi.y, 0.0f);
    *(float4*)&out[(size_t)(node0 + n) * 256 + h * 32 + fq * 4] = r;
}

extern "C" void kernel_launch(void* const* d_in, const int* in_sizes, int n_in,
                              void* d_out, int out_size)
{
    const float* x    = (const float*)d_in[0];
    const float* Wk_  = (const float*)d_in[1];
    const float* bk_  = (const float*)d_in[2];
    const float* Wq_  = (const float*)d_in[3];
    const float* bq_  = (const float*)d_in[4];
    const float* Wv_  = (const float*)d_in[5];
    const float* bv_  = (const float*)d_in[6];
    const float* pri  = (const float*)d_in[7];
    const float* msg  = (const float*)d_in[8];
    const float* pric = (const float*)d_in[9];
    const float* msgc = (const float*)d_in[10];
    const float* cpri = (const float*)d_in[11];
    const float* cauf = (const float*)d_in[12];
    const float* temb = (const float*)d_in[13];
    const int*   ctyp = (const int*)d_in[14];
    const int*   src  = (const int*)d_in[15];
    const int*   dst  = (const int*)d_in[16];
    float* out = (float*)d_out;

    cudaFuncSetAttribute(k_gemm, cudaFuncAttributeMaxDynamicSharedMemorySize, GSMEM);

    k_splitx<<<NN * DD / 256, 256>>>(x);                                // 1 (cnt zero fused)
    k_splitw<<<3 * DD * DD / 256, 256>>>(Wq_, Wk_, Wv_);                // 2
    k_hist  <<<NSLOT / 256, 256>>>(dst);                                // 3
    k_gemm  <<<dim3((NN + 127) / 128, 6), 256, GSMEM>>>(bq_, bk_, bv_); // 4 <- profiled
    k_scan  <<<1, 1024>>>();                                            // 5
    k_fill  <<<NSLOT / 256, 256>>>(src, dst);                           // 6
    k_mk    <<<dim3(NN / 32, HH), 256>>>(cauf, ctyp);                   // 7
    k_edge2 <<<(NSEG + 7) / 8, 256>>>(pri, pric);                       // 8
    k_post  <<<dim3(NN / 32, HH), 256>>>(msg, msgc, cpri, temb, out);   // 9
}

// round 17
// speedup vs baseline: 1.3006x; 1.0572x over previous
#include <cuda_runtime.h>
#include <cuda_bf16.h>
#include <cuda_fp16.h>
#include <cstdint>

#define NN 20000
#define NE 160000
#define HH 8
#define DD 256
#define NSEG (3 * NN)
#define NSLOT (3 * NE)

// ---------------- scratch (static device arrays; no allocation) ----------------
__device__ float g_q[NN * DD];                       // fp32 (read once per segment)
__device__ __align__(16) __half g_kh[NN * DD];       // fp16 k
__device__ __align__(16) __half g_vh[NN * DD];       // fp16 v
__device__ __align__(16) __half g_mkh[NN * DD];      // fp16 masked_k
__device__ __align__(16) __half g_Ah[3][NN * DD];    // fp16 normalized A
__device__ __align__(16) __half g_Ch[3][NN * DD];    // fp16 normalized C
__device__ int   g_cnt[NSEG];
__device__ int   g_off[NSEG + 1];
__device__ int   g_cur[NSEG];
__device__ int   g_csr[NSLOT];
__device__ __align__(16) __nv_bfloat16 g_x1[NN * DD];
__device__ __align__(16) __nv_bfloat16 g_x2[NN * DD];
__device__ __align__(16) __nv_bfloat16 g_B1[3 * DD * DD];  // [mat][n][k] = W[k][n] hi
__device__ __align__(16) __nv_bfloat16 g_B2[3 * DD * DD];  // lo

typedef unsigned long long ull;

__device__ __forceinline__ void ffma2(ull& a, ull x, ull w) {
    asm("fma.rn.f32x2 %0, %1, %2, %0;" : "+l"(a) : "l"(x), "l"(w));
}
__device__ __forceinline__ ull dup2(float v) {
    ull r; asm("mov.b64 %0, {%1, %1};" : "=l"(r) : "f"(v)); return r;
}
union F4U { float4 f; ull u[2]; };
union H2U { __half2 h; unsigned u; };

__device__ __forceinline__ void fma4(float4& a, float s, const float4 b) {
    a.x += s * b.x; a.y += s * b.y; a.z += s * b.z; a.w += s * b.w;
}

__device__ __forceinline__ uint4 pack_half8(float4 a, float4 b, float s) {
    H2U h0, h1, h2, h3;
    h0.h = __floats2half2_rn(a.x * s, a.y * s);
    h1.h = __floats2half2_rn(a.z * s, a.w * s);
    h2.h = __floats2half2_rn(b.x * s, b.y * s);
    h3.h = __floats2half2_rn(b.z * s, b.w * s);
    uint4 r; r.x = h0.u; r.y = h1.u; r.z = h2.u; r.w = h3.u;
    return r;
}
__device__ __forceinline__ void unpack8(uint4 u, float4& lo, float4& hi) {
    float2 a = __half22float2(*(__half2*)&u.x);
    float2 b = __half22float2(*(__half2*)&u.y);
    float2 c = __half22float2(*(__half2*)&u.z);
    float2 d = __half22float2(*(__half2*)&u.w);
    lo = make_float4(a.x, a.y, b.x, b.y);
    hi = make_float4(c.x, c.y, d.x, d.y);
}

__device__ __forceinline__ uint32_t smem_u32(const void* p) {
    uint32_t a;
    asm("{ .reg .u64 t; cvta.to.shared.u64 t, %1; cvt.u32.u64 %0, t; }" : "=r"(a) : "l"(p));
    return a;
}
__device__ __forceinline__ void ldsm4(uint32_t* r, uint32_t addr) {
    asm volatile("ldmatrix.sync.aligned.m8n8.x4.shared.b16 {%0,%1,%2,%3}, [%4];"
                 : "=r"(r[0]), "=r"(r[1]), "=r"(r[2]), "=r"(r[3]) : "r"(addr));
}
__device__ __forceinline__ void mma_bf16(float* d, const uint32_t* a, const uint32_t* b) {
    asm volatile(
        "mma.sync.aligned.m16n8k16.row.col.f32.bf16.bf16.f32 "
        "{%0,%1,%2,%3}, {%4,%5,%6,%7}, {%8,%9}, {%0,%1,%2,%3};"
        : "+f"(d[0]), "+f"(d[1]), "+f"(d[2]), "+f"(d[3])
        : "r"(a[0]), "r"(a[1]), "r"(a[2]), "r"(a[3]), "r"(b[0]), "r"(b[1]));
}
__device__ __forceinline__ void cp16(uint32_t saddr, const void* gptr) {
    asm volatile("cp.async.cg.shared.global [%0], [%1], 16;"
                 :: "r"(saddr), "l"(gptr) : "memory");
}

// ---------------- split kernels (k_zero fused into k_splitx) ----------------
__global__ __launch_bounds__(256) void k_splitx(const float* __restrict__ x) {
    int i = blockIdx.x * 256 + threadIdx.x;
    float v = x[i];
    __nv_bfloat16 h = __float2bfloat16(v);
    g_x1[i] = h;
    g_x2[i] = __float2bfloat16(v - __bfloat162float(h));
    if (i < NSEG) g_cnt[i] = 0;
}

__global__ __launch_bounds__(256) void k_splitw(
    const float* __restrict__ Wq, const float* __restrict__ Wk, const float* __restrict__ Wv)
{
    int i = blockIdx.x * 256 + threadIdx.x;   // [0, 3*65536)
    int mat = i >> 16;
    int rem = i & 65535;
    int kk = rem >> 8;
    int n  = rem & 255;
    const float* W = (mat == 0) ? Wq : (mat == 1) ? Wk : Wv;
    float v = W[kk * DD + n];
    __nv_bfloat16 h = __float2bfloat16(v);
    g_B1[mat * 65536 + n * DD + kk] = h;
    g_B2[mat * 65536 + n * DD + kk] = __float2bfloat16(v - __bfloat162float(h));
}

// ---------------- K1: projections via mma.sync bf16 split-GEMM ----------------
// K chunks of 32 (8 chunks), tile rows 80B (64B data + 16 pad) -> smem/CTA 80KB
// -> 2 CTAs/SM (regs capped 128 by launch_bounds). Tensor-pipe util ~2x.
#define RSTR  80              // row stride bytes (16-aligned; conflict-free mod 128)
#define TSZ   (128 * RSTR)    // 10240
#define BUFSZ (4 * TSZ)       // 40960
#define GSMEM (2 * BUFSZ)     // 81920
#define NCH   8               // 256 / 32

__global__ __launch_bounds__(256, 2) void k_gemm(
    const float* __restrict__ bq, const float* __restrict__ bk, const float* __restrict__ bv)
{
    extern __shared__ char smem[];
    const uint32_t sb = smem_u32(smem);
    const int tid = threadIdx.x, wid = tid >> 5, lane = tid & 31;
    const int m0  = blockIdx.x * 128;
    const int sel = blockIdx.y;
    const int mat = sel >> 1;
    const int n0  = (sel & 1) * 128;
    const size_t bbase = (size_t)mat * 65536;

    const int m_off = (wid >> 2) * 64;
    const int n_off = (wid & 3) * 32;

    const int aj = lane >> 3;
    const int a_row = (lane & 7) + 8 * (aj & 1);
    const int a_kof = 8 * (aj >> 1);
    const int b_nof = (lane & 7) + 8 * (aj >> 1);
    const int b_kof = 8 * (aj & 1);

    // loader: 4 tiles x 128 rows x 64B data; thread covers 16B
    // 1024 (rows*4B-groups) per tile: L = tile*1024 + row*4 + c16? Use:
    // per tile: 128 rows x 4 x 16B = 8192B... data region is 64B/row -> 4 cp16 per row.
    auto load_chunk = [&](int c) {
        const int k0 = c * 32;
        const uint32_t bufb = sb + (c & 1) * BUFSZ;
        #pragma unroll
        for (int i = 0; i < 8; i++) {
            int L = i * 256 + tid;          // [0, 2048) = 4 tiles * 512
            int tile = L >> 9;
            int r = L & 511;                // 128 rows * 4 quads
            int row = r >> 2;
            int c16 = r & 3;
            uint32_t saddr = bufb + tile * TSZ + row * RSTR + c16 * 16;
            const __nv_bfloat16* gp;
            if (tile < 2) {
                int node = min(m0 + row, NN - 1);
                gp = (tile == 0 ? g_x1 : g_x2) + (size_t)node * DD + k0 + c16 * 8;
            } else {
                int nrow = n0 + row;
                gp = (tile == 2 ? g_B1 : g_B2) + bbase + (size_t)nrow * DD + k0 + c16 * 8;
            }
            cp16(saddr, gp);
        }
        asm volatile("cp.async.commit_group;" ::: "memory");
    };

    float dacc[4][4][4];
    #pragma unroll
    for (int mf = 0; mf < 4; mf++)
        #pragma unroll
        for (int nf = 0; nf < 4; nf++)
            #pragma unroll
            for (int rr = 0; rr < 4; rr++) dacc[mf][nf][rr] = 0.0f;

    load_chunk(0);

    #pragma unroll 1
    for (int c = 0; c < NCH; c++) {
        if (c + 1 < NCH) {
            load_chunk(c + 1);
            asm volatile("cp.async.wait_group 1;" ::: "memory");
        } else {
            asm volatile("cp.async.wait_group 0;" ::: "memory");
        }
        __syncthreads();

        const uint32_t bufb = sb + (c & 1) * BUFSZ;
        const uint32_t A1b = bufb + 0 * TSZ;
        const uint32_t A2b = bufb + 1 * TSZ;
        const uint32_t B1b = bufb + 2 * TSZ;
        const uint32_t B2b = bufb + 3 * TSZ;

        #pragma unroll
        for (int ks = 0; ks < 2; ks++) {
            const int k16 = ks * 16;
            uint32_t af[4][4];
            uint32_t b1f[4][2], b2f[4][2];

            #pragma unroll
            for (int mf = 0; mf < 4; mf++)
                ldsm4(af[mf], A1b + (m_off + mf * 16 + a_row) * RSTR + (k16 + a_kof) * 2);
            #pragma unroll
            for (int p = 0; p < 2; p++) {
                uint32_t t4[4];
                ldsm4(t4, B1b + (n_off + p * 16 + b_nof) * RSTR + (k16 + b_kof) * 2);
                b1f[p * 2][0] = t4[0]; b1f[p * 2][1] = t4[1];
                b1f[p * 2 + 1][0] = t4[2]; b1f[p * 2 + 1][1] = t4[3];
                ldsm4(t4, B2b + (n_off + p * 16 + b_nof) * RSTR + (k16 + b_kof) * 2);
                b2f[p * 2][0] = t4[0]; b2f[p * 2][1] = t4[1];
                b2f[p * 2 + 1][0] = t4[2]; b2f[p * 2 + 1][1] = t4[3];
            }

            #pragma unroll
            for (int mf = 0; mf < 4; mf++)
                #pragma unroll
                for (int nf = 0; nf < 4; nf++)
                    mma_bf16(dacc[mf][nf], af[mf], b1f[nf]);
            #pragma unroll
            for (int mf = 0; mf < 4; mf++)
                #pragma unroll
                for (int nf = 0; nf < 4; nf++)
                    mma_bf16(dacc[mf][nf], af[mf], b2f[nf]);

            #pragma unroll
            for (int mf = 0; mf < 4; mf++)
                ldsm4(af[mf], A2b + (m_off + mf * 16 + a_row) * RSTR + (k16 + a_kof) * 2);
            #pragma unroll
            for (int mf = 0; mf < 4; mf++)
                #pragma unroll
                for (int nf = 0; nf < 4; nf++)
                    mma_bf16(dacc[mf][nf], af[mf], b1f[nf]);
        }
        __syncthreads();
    }

    const float* bias = (mat == 0) ? bq : (mat == 1) ? bk : bv;
    __half* Oh = (mat == 1) ? g_kh : g_vh;

    const int trow = lane >> 2;
    const int tcol = (lane & 3) * 2;
    #pragma unroll
    for (int nf = 0; nf < 4; nf++) {
        int gcol = n0 + n_off + nf * 8 + tcol;
        float bx = bias[gcol], by = bias[gcol + 1];
        #pragma unroll
        for (int mf = 0; mf < 4; mf++) {
            int r0 = m0 + m_off + mf * 16 + trow;
            int r1 = r0 + 8;
            if (mat == 0) {
                if (r0 < NN) {
                    float2 v0 = make_float2(dacc[mf][nf][0] + bx, dacc[mf][nf][1] + by);
                    *(float2*)&g_q[(size_t)r0 * DD + gcol] = v0;
                }
                if (r1 < NN) {
                    float2 v1 = make_float2(dacc[mf][nf][2] + bx, dacc[mf][nf][3] + by);
                    *(float2*)&g_q[(size_t)r1 * DD + gcol] = v1;
                }
            } else {
                if (r0 < NN) {
                    H2U h; h.h = __floats2half2_rn(dacc[mf][nf][0] + bx, dacc[mf][nf][1] + by);
                    *(unsigned*)&Oh[(size_t)r0 * DD + gcol] = h.u;
                }
                if (r1 < NN) {
                    H2U h; h.h = __floats2half2_rn(dacc[mf][nf][2] + bx, dacc[mf][nf][3] + by);
                    *(unsigned*)&Oh[(size_t)r1 * DD + gcol] = h.u;
                }
            }
        }
    }
}

// ---------------- CSR build ----------------
__global__ __launch_bounds__(256) void k_hist(const int* __restrict__ dst) {
    int idx = blockIdx.x * 256 + threadIdx.x;
    int e = idx / NE;
    atomicAdd(&g_cnt[e * NN + dst[idx]], 1);
}

#define SCHUNK 59
__global__ __launch_bounds__(1024) void k_scan() {
    __shared__ int ssum[1024];
    int t = threadIdx.x;
    int base = t * SCHUNK;
    int s = 0;
    #pragma unroll 4
    for (int i = 0; i < SCHUNK; i++) {
        int idx = base + i;
        if (idx < NSEG) s += g_cnt[idx];
    }
    ssum[t] = s;
    __syncthreads();
    for (int off = 1; off < 1024; off <<= 1) {
        int v = 0;
        if (t >= off) v = ssum[t - off];
        __syncthreads();
        if (t >= off) ssum[t] += v;
        __syncthreads();
    }
    int run = (t == 0) ? 0 : ssum[t - 1];
    for (int i = 0; i < SCHUNK; i++) {
        int idx = base + i;
        if (idx < NSEG) {
            int c = g_cnt[idx];
            g_off[idx] = run;
            g_cur[idx] = run;
            run += c;
        }
    }
    if (t == 0) g_off[NSEG] = ssum[1023];
}

__global__ __launch_bounds__(256) void k_fill(const int* __restrict__ src,
                                              const int* __restrict__ dst) {
    int idx = blockIdx.x * 256 + threadIdx.x;
    int e = idx / NE;
    int pos = atomicAdd(&g_cur[e * NN + dst[idx]], 1);
    g_csr[pos] = src[idx];
}

// ---------------- K2: masked_k (fp16 in, fp32 math, fp16 out) ----------------
__global__ __launch_bounds__(256) void k_mk(
    const float* __restrict__ cau_filter, const int* __restrict__ cau_type)
{
    const int h     = blockIdx.y;
    const int node0 = blockIdx.x * 32;
    const int tid   = threadIdx.x;

    __shared__ __align__(16) float Ff[3][1024];
    __shared__ float kt[32 * 33];

    #pragma unroll
    for (int e = 0; e < 3; e++)
        #pragma unroll
        for (int i = 0; i < 4; i++) {
            int idx = i * 256 + tid;
            Ff[e][idx] = cau_filter[(size_t)(e * HH + h) * 1024 + idx];
        }
    #pragma unroll
    for (int i = 0; i < 4; i++) {
        int lin = i * 256 + tid;
        int n = lin >> 5, d = lin & 31;
        kt[n * 33 + d] = __half2float(g_kh[(size_t)(node0 + n) * 256 + h * 32 + d]);
    }
    __syncthreads();

    const int n  = tid >> 3;
    const int fq = tid & 7;
    const int ct = cau_type[node0 + n];
    const float4* Ffp = (const float4*)Ff[ct];

    float4 mk = make_float4(0,0,0,0);
    #pragma unroll 8
    for (int d = 0; d < 32; d++)
        fma4(mk, kt[n * 33 + d], Ffp[d * 8 + fq]);

    H2U h0, h1;
    h0.h = __floats2half2_rn(mk.x, mk.y);
    h1.h = __floats2half2_rn(mk.z, mk.w);
    uint2 packed; packed.x = h0.u; packed.y = h1.u;
    *(uint2*)&g_mkh[(size_t)(node0 + n) * 256 + h * 32 + fq * 4] = packed;
}

// ---------------- K3: warp-per-(e,d) segment — fp16 gathers ----------------
__global__ __launch_bounds__(256) void k_edge2(
    const float* __restrict__ pri, const float* __restrict__ pri_cau)
{
    int wseg = blockIdx.x * 8 + (threadIdx.x >> 5);
    if (wseg >= NSEG) return;
    int e = wseg / NN;
    int d = wseg - e * NN;
    int lane = threadIdx.x & 31;
    int h = lane >> 2;
    int off = h * 32 + (lane & 3) * 8;

    int beg = g_off[wseg];
    int end = g_off[wseg + 1];

    const float inv = 0.17677669529663688f;
    float pe  = pri[e * 8 + h] * inv;
    float pce = pri_cau[e * 8 + h] * inv;

    const float4* qp = (const float4*)(g_q + (size_t)d * 256 + off);
    float4 q0 = qp[0], q1 = qp[1];

    float4 A0 = make_float4(0,0,0,0), A1 = make_float4(0,0,0,0);
    float4 C0 = make_float4(0,0,0,0), C1 = make_float4(0,0,0,0);
    float sum = 0.0f, csum = 0.0f;

    for (int slot = beg; slot < end; slot++) {
        int s = g_csr[slot];
        uint4 ku = *(const uint4*)(g_kh  + (size_t)s * 256 + off);
        uint4 mu = *(const uint4*)(g_mkh + (size_t)s * 256 + off);
        uint4 vu = *(const uint4*)(g_vh  + (size_t)s * 256 + off);
        float4 k0, k1, m0, m1, v0, v1;
        unpack8(ku, k0, k1);
        unpack8(mu, m0, m1);
        unpack8(vu, v0, v1);

        float p  = q0.x*k0.x + q0.y*k0.y + q0.z*k0.z + q0.w*k0.w
                 + q1.x*k1.x + q1.y*k1.y + q1.z*k1.z + q1.w*k1.w;
        float pc = q0.x*m0.x + q0.y*m0.y + q0.z*m0.z + q0.w*m0.w
                 + q1.x*m1.x + q1.y*m1.y + q1.z*m1.z + q1.w*m1.w;
        p  += __shfl_xor_sync(0xffffffffu, p, 1);
        p  += __shfl_xor_sync(0xffffffffu, p, 2);
        pc += __shfl_xor_sync(0xffffffffu, pc, 1);
        pc += __shfl_xor_sync(0xffffffffu, pc, 2);

        // logits ~ N(0,1): exp safe; softmax shift-invariant -> no segment max
        float ea  = __expf(p * pe);
        float cea = __expf(pc * pce);

        fma4(A0, ea, v0);  fma4(A1, ea, v1);
        fma4(C0, cea, v0); fma4(C1, cea, v1);
        sum += ea; csum += cea;
    }

    float ia = (end > beg) ? 1.0f / (3.0f * sum)  : 0.0f;
    float ic = (end > beg) ? 1.0f / (3.0f * csum) : 0.0f;

    *(uint4*)&g_Ah[e][(size_t)d * 256 + off] = pack_half8(A0, A1, ia);
    *(uint4*)&g_Ch[e][(size_t)d * 256 + off] = pack_half8(C0, C1, ic);
}

// ---------------- K4: deferred transforms + mean + relu (f32x2) ----------------
__global__ __launch_bounds__(256) void k_post(
    const float* __restrict__ msg, const float* __restrict__ msg_cau,
    const float* __restrict__ comb_pri, const float* __restrict__ time_emb,
    float* __restrict__ out)
{
    const int h     = blockIdx.y;
    const int node0 = blockIdx.x * 32;
    const int tid   = threadIdx.x;

    __shared__ __align__(16) float Mm[3][1024];
    __shared__ __align__(16) float Mc[3][1024];
    __shared__ float at[3][32 * 33];
    __shared__ float ct[3][32 * 33];
    __shared__ float swc_s[3][32];

    #pragma unroll
    for (int e = 0; e < 3; e++)
        #pragma unroll
        for (int i = 0; i < 4; i++) {
            int idx = i * 256 + tid;
            Mm[e][idx] = msg[(size_t)(e * HH + h) * 1024 + idx];
            Mc[e][idx] = msg_cau[(size_t)(e * HH + h) * 1024 + idx]
                       * comb_pri[e * 256 + h * 32 + (idx & 31)];
        }
    if (tid < 96) {
        int e = tid >> 5, n = tid & 31;
        int seg = e * NN + node0 + n;
        swc_s[e][n] = (g_off[seg + 1] > g_off[seg]) ? (1.0f / 3.0f) : 0.0f;
    }
    __syncthreads();

    #pragma unroll
    for (int e = 0; e < 3; e++)
        #pragma unroll
        for (int i = 0; i < 4; i++) {
            int lin = i * 256 + tid;
            int n = lin >> 5, dd = lin & 31;
            int node = node0 + n;
            at[e][n * 33 + dd] = __half2float(g_Ah[e][(size_t)node * 256 + h * 32 + dd]);
            ct[e][n * 33 + dd] = __half2float(g_Ch[e][(size_t)node * 256 + h * 32 + dd])
                               + swc_s[e][n] * time_emb[h * 32 + dd];
        }
    __syncthreads();

    const int n  = tid >> 3;
    const int fq = tid & 7;

    ull a0 = 0ull, a1 = 0ull;
    #pragma unroll
    for (int e = 0; e < 3; e++) {
        const float4* Mmp = (const float4*)Mm[e];
        const float4* Mcp = (const float4*)Mc[e];
        #pragma unroll 8
        for (int d = 0; d < 32; d++) {
            ull ax = dup2(at[e][n * 33 + d]);
            ull cx = dup2(ct[e][n * 33 + d]);
            F4U m; m.f = Mmp[d * 8 + fq];
            F4U c; c.f = Mcp[d * 8 + fq];
            ffma2(a0, ax, m.u[0]); ffma2(a1, ax, m.u[1]);
            ffma2(a0, cx, c.u[0]); ffma2(a1, cx, c.u[1]);
        }
    }

    float2 lo = *(float2*)&a0;
    float2 hi = *(float2*)&a1;
    float4 r;
    r.x = fmaxf(lo.x, 0.0f); r.y = fmaxf(lo.y, 0.0f);
    r.z = fmaxf(hi.x, 0.0f); r.w = fmaxf(hi.y, 0.0f);
    *(float4*)&out[(size_t)(node0 + n) * 256 + h * 32 + fq * 4] = r;
}

extern "C" void kernel_launch(void* const* d_in, const int* in_sizes, int n_in,
                              void* d_out, int out_size)
{
    const float* x    = (const float*)d_in[0];
    const float* Wk_  = (const float*)d_in[1];
    const float* bk_  = (const float*)d_in[2];
    const float* Wq_  = (const float*)d_in[3];
    const float* bq_  = (const float*)d_in[4];
    const float* Wv_  = (const float*)d_in[5];
    const float* bv_  = (const float*)d_in[6];
    const float* pri  = (const float*)d_in[7];
    const float* msg  = (const float*)d_in[8];
    const float* pric = (const float*)d_in[9];
    const float* msgc = (const float*)d_in[10];
    const float* cpri = (const float*)d_in[11];
    const float* cauf = (const float*)d_in[12];
    const float* temb = (const float*)d_in[13];
    const int*   ctyp = (const int*)d_in[14];
    const int*   src  = (const int*)d_in[15];
    const int*   dst  = (const int*)d_in[16];
    float* out = (float*)d_out;

    cudaFuncSetAttribute(k_gemm, cudaFuncAttributeMaxDynamicSharedMemorySize, GSMEM);

    k_splitx<<<NN * DD / 256, 256>>>(x);                                // 1 (cnt zero fused)
    k_splitw<<<3 * DD * DD / 256, 256>>>(Wq_, Wk_, Wv_);                // 2
    k_hist  <<<NSLOT / 256, 256>>>(dst);                                // 3
    k_gemm  <<<dim3((NN + 127) / 128, 6), 256, GSMEM>>>(bq_, bk_, bv_); // 4 <- profiled
    k_scan  <<<1, 1024>>>();                                            // 5
    k_fill  <<<NSLOT / 256, 256>>>(src, dst);                           // 6
    k_mk    <<<dim3(NN / 32, HH), 256>>>(cauf, ctyp);                   // 7
    k_edge2 <<<(NSEG + 7) / 8, 256>>>(pri, pric);                       // 8
    k_post  <<<dim3(NN / 32, HH), 256>>>(msg, msgc, cpri, temb, out);   // 9
}